// round 1
// baseline (speedup 1.0000x reference)
#include <cuda_runtime.h>
#include <math.h>

#define BB 64
#define NN 512
#define EE 8192
#define HH 128
#define MM (BB*NN)   // 32768

// ---------------- scratch (static device allocations) ----------------
__device__ float g_X0 [(size_t)MM*256];
__device__ float g_X1 [(size_t)MM*128];
__device__ float g_Ab [(size_t)MM*128];
__device__ float g_Hb [(size_t)MM*128];
__device__ float g_pos[(size_t)MM*128];
__device__ float g_dinv [3*MM];
__device__ int   g_offs [3*BB*(NN+1)];
__device__ int   g_ssrc [3*BB*EE];
__device__ float g_snorm[3*BB*EE];
__device__ float g_roots[3*BB*HH];

// ---------------- prep: degrees, dinv, dst-sorted CSR + norms ----------------
__global__ void prep_kernel(const int* __restrict__ edges, int slot) {
    int b = blockIdx.x;
    const int* src = edges + (size_t)b*2*EE;
    const int* dst = src + EE;
    __shared__ int   cnt[NN];
    __shared__ float sdinv[NN];
    __shared__ int   base[NN+1];
    int t = threadIdx.x, nt = blockDim.x;

    for (int n = t; n < NN; n += nt) cnt[n] = 0;
    __syncthreads();
    for (int e = t; e < EE; e += nt) atomicAdd(&cnt[dst[e]], 1);
    __syncthreads();
    for (int n = t; n < NN; n += nt) {
        float d = (float)(cnt[n] + 1);          // +1 self loop
        float di = rsqrtf(d);
        sdinv[n] = di;
        g_dinv[slot*MM + b*NN + n] = di;
    }
    __syncthreads();
    if (t == 0) {
        int s = 0;
        for (int n = 0; n < NN; n++) { base[n] = s; s += cnt[n]; }
        base[NN] = s;
    }
    __syncthreads();
    for (int n = t; n <= NN; n += nt)
        g_offs[(slot*BB + b)*(NN+1) + n] = base[n];
    for (int n = t; n < NN; n += nt) cnt[n] = 0;   // reuse as cursor
    __syncthreads();
    int* osrc = g_ssrc + (slot*BB + b)*EE;
    float* onm = g_snorm + (slot*BB + b)*EE;
    for (int e = t; e < EE; e += nt) {
        int d = dst[e], s = src[e];
        int p = base[d] + atomicAdd(&cnt[d], 1);
        osrc[p] = s;
        onm[p]  = sdinv[s] * sdinv[d];
    }
}

// ---------------- build X0 = [embedA | features] ----------------
__global__ void build_x0_kernel(const float* __restrict__ embA, const int* __restrict__ idxA,
                                int perBatch, const float* __restrict__ feat,
                                const int* __restrict__ idxF) {
    int t = blockIdx.x * blockDim.x + threadIdx.x;   // MM*64 threads (float4 each)
    int row = t >> 6;
    int q   = t & 63;
    int b   = row >> 9;
    float4 v;
    if (q < 32) {
        int idx = idxA[row];
        size_t sr = perBatch ? ((size_t)b*NN + idx) : (size_t)idx;
        v = *(const float4*)(embA + sr*128 + q*4);
    } else {
        int idx = idxF[row];
        v = *(const float4*)(feat + (size_t)idx*128 + (q-32)*4);
    }
    *(float4*)(g_X0 + (size_t)row*256 + q*4) = v;
}

// ---------------- fp32 tiled GEMM: C[M,128] = act(A[M,K] @ W[K,128] + bias) ----------------
__global__ __launch_bounds__(256) void gemm_kernel(const float* __restrict__ A,
                                                   const float* __restrict__ W,
                                                   const float* __restrict__ bias,
                                                   float* __restrict__ C,
                                                   int K, int act) {
    const int BM = 64, BK = 32;
    __shared__ float As[BK][BM];       // transposed A tile
    __shared__ float Ws[BK][128];
    int tid  = threadIdx.x;
    int row0 = blockIdx.x * BM;
    int tcol = tid & 31;               // cols tcol*4 .. +3
    int trow = tid >> 5;               // rows trow*8 .. +7
    float acc[8][4];
    #pragma unroll
    for (int i = 0; i < 8; i++)
        #pragma unroll
        for (int j = 0; j < 4; j++) acc[i][j] = 0.f;

    for (int kb = 0; kb < K; kb += BK) {
        #pragma unroll
        for (int l = 0; l < 2; l++) {
            int idx = tid + l*256;                 // 0..511
            int r   = idx >> 3;
            int c4  = idx & 7;
            float4 v = *(const float4*)(A + (size_t)(row0 + r)*K + kb + c4*4);
            As[c4*4+0][r] = v.x; As[c4*4+1][r] = v.y;
            As[c4*4+2][r] = v.z; As[c4*4+3][r] = v.w;
        }
        #pragma unroll
        for (int l = 0; l < 4; l++) {
            int idx = tid + l*256;                 // 0..1023
            int r   = idx >> 5;
            int c4  = idx & 31;
            *(float4*)&Ws[r][c4*4] = *(const float4*)(W + (size_t)(kb + r)*128 + c4*4);
        }
        __syncthreads();
        #pragma unroll
        for (int kk = 0; kk < BK; kk++) {
            float4 a0 = *(const float4*)&As[kk][trow*8];
            float4 a1 = *(const float4*)&As[kk][trow*8 + 4];
            float4 w  = *(const float4*)&Ws[kk][tcol*4];
            float av[8] = {a0.x,a0.y,a0.z,a0.w,a1.x,a1.y,a1.z,a1.w};
            #pragma unroll
            for (int i = 0; i < 8; i++) {
                acc[i][0] += av[i]*w.x; acc[i][1] += av[i]*w.y;
                acc[i][2] += av[i]*w.z; acc[i][3] += av[i]*w.w;
            }
        }
        __syncthreads();
    }
    float4 bb = make_float4(0.f,0.f,0.f,0.f);
    if (bias) bb = *(const float4*)(bias + tcol*4);
    #pragma unroll
    for (int i = 0; i < 8; i++) {
        float4 o = make_float4(acc[i][0]+bb.x, acc[i][1]+bb.y,
                               acc[i][2]+bb.z, acc[i][3]+bb.w);
        if (act) {
            o.x = fmaxf(o.x,0.f); o.y = fmaxf(o.y,0.f);
            o.z = fmaxf(o.z,0.f); o.w = fmaxf(o.w,0.f);
        }
        *(float4*)(C + (size_t)(row0 + trow*8 + i)*128 + tcol*4) = o;
    }
}

// ---------------- GCN aggregation via CSR gather: one warp per dst node ----------------
__global__ void agg_kernel(const float* __restrict__ h, int slot,
                           const float* __restrict__ bias,
                           float* __restrict__ outbuf, int relu) {
    int gw   = (blockIdx.x * blockDim.x + threadIdx.x) >> 5;
    int lane = threadIdx.x & 31;
    if (gw >= MM) return;
    int b = gw >> 9;
    int n = gw & (NN-1);
    const float* dinv  = g_dinv + slot*MM + b*NN;
    const int*   offs  = g_offs + (slot*BB + b)*(NN+1);
    const int*   ssrc  = g_ssrc + (slot*BB + b)*EE;
    const float* snorm = g_snorm + (slot*BB + b)*EE;
    const float* hb = h + (size_t)b*NN*128;

    float di = dinv[n];
    float4 hv = *(const float4*)(hb + (size_t)n*128 + lane*4);
    float self = di*di;
    float4 acc = make_float4(hv.x*self, hv.y*self, hv.z*self, hv.w*self);

    int beg = offs[n], end = offs[n+1];
    for (int j = beg; j < end; j++) {
        int   s  = ssrc[j];
        float nm = snorm[j];
        float4 v = *(const float4*)(hb + (size_t)s*128 + lane*4);
        acc.x += v.x*nm; acc.y += v.y*nm; acc.z += v.z*nm; acc.w += v.w*nm;
    }
    float4 bb = make_float4(0.f,0.f,0.f,0.f);
    if (bias) bb = *(const float4*)(bias + lane*4);
    float4 o = make_float4(acc.x+bb.x, acc.y+bb.y, acc.z+bb.z, acc.w+bb.w);
    if (relu) {
        o.x = fmaxf(o.x,0.f); o.y = fmaxf(o.y,0.f);
        o.z = fmaxf(o.z,0.f); o.w = fmaxf(o.w,0.f);
    }
    *(float4*)(outbuf + (size_t)gw*128 + lane*4) = o;
}

// ---------------- gather root rows ----------------
__global__ void gather_root_kernel(const float* __restrict__ src,
                                   const int* __restrict__ root_idx, int slot) {
    int b = blockIdx.x;
    int lane = threadIdx.x;   // 32
    int r = root_idx[b];
    float4 v = *(const float4*)(src + ((size_t)b*NN + r)*128 + lane*4);
    *(float4*)(g_roots + (size_t)(slot*BB + b)*HH + lane*4) = v;
}

// ---------------- score heads: sigmoid(relu(r@W1+b1)@W2+b2) ----------------
__global__ void score_kernel(const float* __restrict__ W1a, const float* __restrict__ b1a,
                             const float* __restrict__ W2a, const float* __restrict__ b2a,
                             const float* __restrict__ W1b, const float* __restrict__ b1b,
                             const float* __restrict__ W2b, const float* __restrict__ b2b,
                             float* __restrict__ out) {
    int combo = blockIdx.x;        // 0:(pos,m0) 1:(pos,m1) 2:(m1,m0) 3:(m2,m1)
    int b     = blockIdx.y;
    int t     = threadIdx.x;       // 128
    int rs = (combo < 2) ? 0 : (combo - 1);
    int ms = combo & 1;
    const float* W1 = ms ? W1b : W1a;
    const float* b1 = ms ? b1b : b1a;
    const float* W2 = ms ? W2b : W2a;
    const float* b2 = ms ? b2b : b2a;

    __shared__ float r[128];
    r[t] = g_roots[(size_t)(rs*BB + b)*HH + t];
    __syncthreads();

    float hsum = b1[t];
    #pragma unroll 8
    for (int k = 0; k < 128; k++) hsum += r[k] * W1[k*128 + t];
    hsum = fmaxf(hsum, 0.f);
    float p = hsum * W2[t];

    int lane = t & 31, warp = t >> 5;
    #pragma unroll
    for (int off = 16; off; off >>= 1) p += __shfl_down_sync(0xffffffff, p, off);
    __shared__ float ws[4];
    if (lane == 0) ws[warp] = p;
    __syncthreads();
    if (t == 0) {
        float s = ws[0] + ws[1] + ws[2] + ws[3] + b2[0];
        out[combo*BB + b] = 1.f / (1.f + expf(-s));
    }
}

// ---------------- host orchestration ----------------
extern "C" void kernel_launch(void* const* d_in, const int* in_sizes, int n_in,
                              void* d_out, int out_size) {
    const int* node_ids    = (const int*)d_in[0];
    const int* edge_pos    = (const int*)d_in[1];
    const int* root_idx    = (const int*)d_in[2];
    const int* mal_nodes1  = (const int*)d_in[3];
    const int* mal_posidx1 = (const int*)d_in[4];
    const int* edge_m1     = (const int*)d_in[5];
    const int* mal_nodes2  = (const int*)d_in[6];
    const int* mal_posidx2 = (const int*)d_in[7];
    const int* edge_m2     = (const int*)d_in[8];
    const float* embeddings = (const float*)d_in[9];
    const float* features   = (const float*)d_in[10];
    const float* fe_W1 = (const float*)d_in[11];
    const float* fe_b1 = (const float*)d_in[12];
    const float* fe_W2 = (const float*)d_in[13];
    const float* fe_b2 = (const float*)d_in[14];
    const float* g1_W  = (const float*)d_in[15];
    const float* g1_b  = (const float*)d_in[16];
    const float* g2_W  = (const float*)d_in[17];
    const float* g2_b  = (const float*)d_in[18];
    const float* mlp_W1  = (const float*)d_in[19];
    const float* mlp_b1  = (const float*)d_in[20];
    const float* mlp_W2  = (const float*)d_in[21];
    const float* mlp_b2  = (const float*)d_in[22];
    const float* mlp1_W1 = (const float*)d_in[23];
    const float* mlp1_b1 = (const float*)d_in[24];
    const float* mlp1_W2 = (const float*)d_in[25];
    const float* mlp1_b2 = (const float*)d_in[26];
    float* out = (float*)d_out;

    float *X0, *X1, *Ab, *Hb, *Pos;
    cudaGetSymbolAddress((void**)&X0,  g_X0);
    cudaGetSymbolAddress((void**)&X1,  g_X1);
    cudaGetSymbolAddress((void**)&Ab,  g_Ab);
    cudaGetSymbolAddress((void**)&Hb,  g_Hb);
    cudaGetSymbolAddress((void**)&Pos, g_pos);

    const int GEMM_GRID = MM / 64;           // 512
    const int AGG_GRID  = MM / 8;            // 4096 blocks of 256 (=8 warps)
    const int BX0_GRID  = (MM * 64) / 256;   // 8192

    // CSR prep for all three edge sets
    prep_kernel<<<BB, 256>>>(edge_pos, 0);
    prep_kernel<<<BB, 256>>>(edge_m1, 1);
    prep_kernel<<<BB, 256>>>(edge_m2, 2);

    // ---- positive branch ----
    build_x0_kernel<<<BX0_GRID, 256>>>(embeddings, node_ids, 0, features, node_ids);
    gemm_kernel<<<GEMM_GRID, 256>>>(X0, fe_W1, fe_b1, X1, 256, 1);
    gemm_kernel<<<GEMM_GRID, 256>>>(X1, fe_W2, fe_b2, Ab, 128, 0);
    gemm_kernel<<<GEMM_GRID, 256>>>(Ab, g1_W, nullptr, Hb, 128, 0);
    agg_kernel <<<AGG_GRID, 256>>>(Hb, 0, g1_b, X1, 1);
    gemm_kernel<<<GEMM_GRID, 256>>>(X1, g2_W, nullptr, Hb, 128, 0);
    agg_kernel <<<AGG_GRID, 256>>>(Hb, 0, g2_b, Pos, 0);
    gather_root_kernel<<<BB, 32>>>(Pos, root_idx, 0);

    // ---- malicious branch 1 ----
    build_x0_kernel<<<BX0_GRID, 256>>>(Pos, mal_posidx1, 1, features, mal_nodes1);
    gemm_kernel<<<GEMM_GRID, 256>>>(X0, fe_W1, fe_b1, X1, 256, 1);
    gemm_kernel<<<GEMM_GRID, 256>>>(X1, fe_W2, fe_b2, Ab, 128, 0);
    gemm_kernel<<<GEMM_GRID, 256>>>(Ab, g1_W, nullptr, Hb, 128, 0);
    agg_kernel <<<AGG_GRID, 256>>>(Hb, 1, g1_b, X1, 1);
    gemm_kernel<<<GEMM_GRID, 256>>>(X1, g2_W, nullptr, Hb, 128, 0);
    agg_kernel <<<AGG_GRID, 256>>>(Hb, 1, g2_b, Ab, 0);
    gather_root_kernel<<<BB, 32>>>(Ab, root_idx, 1);

    // ---- malicious branch 2 ----
    build_x0_kernel<<<BX0_GRID, 256>>>(Pos, mal_posidx2, 1, features, mal_nodes2);
    gemm_kernel<<<GEMM_GRID, 256>>>(X0, fe_W1, fe_b1, X1, 256, 1);
    gemm_kernel<<<GEMM_GRID, 256>>>(X1, fe_W2, fe_b2, Ab, 128, 0);
    gemm_kernel<<<GEMM_GRID, 256>>>(Ab, g1_W, nullptr, Hb, 128, 0);
    agg_kernel <<<AGG_GRID, 256>>>(Hb, 2, g1_b, X1, 1);
    gemm_kernel<<<GEMM_GRID, 256>>>(X1, g2_W, nullptr, Hb, 128, 0);
    agg_kernel <<<AGG_GRID, 256>>>(Hb, 2, g2_b, Ab, 0);
    gather_root_kernel<<<BB, 32>>>(Ab, root_idx, 2);

    // ---- score heads ----
    score_kernel<<<dim3(4, BB), 128>>>(mlp_W1, mlp_b1, mlp_W2, mlp_b2,
                                       mlp1_W1, mlp1_b1, mlp1_W2, mlp1_b2, out);
    (void)in_sizes; (void)n_in; (void)out_size;
}

// round 2
// speedup vs baseline: 1.1195x; 1.1195x over previous
#include <cuda_runtime.h>
#include <math.h>

#define BB 64
#define NN 512
#define EE 8192
#define HH 128
#define MM (BB*NN)   // 32768
#define MM2 (2*MM)

// ---------------- scratch (static device allocations) ----------------
__device__ float g_X0 [(size_t)MM2*256];
__device__ float g_X1 [(size_t)MM2*128];
__device__ float g_Ab [(size_t)MM2*128];
__device__ float g_Hb [(size_t)MM2*128];
__device__ float g_pos[(size_t)MM*128];
__device__ float g_dinv [3*MM];
__device__ int   g_offs [3*BB*(NN+1)];
__device__ int   g_ssrc [3*BB*EE];
__device__ float g_snorm[3*BB*EE];
__device__ float g_roots[3*BB*HH];

// ---------------- packed f32x2 helpers ----------------
__device__ __forceinline__ unsigned long long dup2(float x) {
    unsigned int u = __float_as_uint(x);
    unsigned long long r;
    asm("mov.b64 %0, {%1, %2};" : "=l"(r) : "r"(u), "r"(u));
    return r;
}
__device__ __forceinline__ unsigned long long fma2(unsigned long long a,
                                                   unsigned long long b,
                                                   unsigned long long c) {
    unsigned long long d;
    asm("fma.rn.f32x2 %0, %1, %2, %3;" : "=l"(d) : "l"(a), "l"(b), "l"(c));
    return d;
}
__device__ __forceinline__ void unpk(unsigned long long v, float& lo, float& hi) {
    unsigned int a, b;
    asm("mov.b64 {%0, %1}, %2;" : "=r"(a), "=r"(b) : "l"(v));
    lo = __uint_as_float(a); hi = __uint_as_float(b);
}

// ---------------- prep: degrees, dinv, dst-sorted CSR + norms ----------------
__global__ void prep_kernel(const int* __restrict__ edges, int slot) {
    int b = blockIdx.x;
    const int* src = edges + (size_t)b*2*EE;
    const int* dst = src + EE;
    __shared__ int   cnt[NN];
    __shared__ float sdinv[NN];
    __shared__ int   base[NN+1];
    int t = threadIdx.x, nt = blockDim.x;

    for (int n = t; n < NN; n += nt) cnt[n] = 0;
    __syncthreads();
    for (int e = t; e < EE; e += nt) atomicAdd(&cnt[dst[e]], 1);
    __syncthreads();
    for (int n = t; n < NN; n += nt) {
        float d = (float)(cnt[n] + 1);          // +1 self loop
        float di = rsqrtf(d);
        sdinv[n] = di;
        g_dinv[slot*MM + b*NN + n] = di;
    }
    __syncthreads();
    if (t == 0) {
        int s = 0;
        for (int n = 0; n < NN; n++) { base[n] = s; s += cnt[n]; }
        base[NN] = s;
    }
    __syncthreads();
    for (int n = t; n <= NN; n += nt)
        g_offs[(slot*BB + b)*(NN+1) + n] = base[n];
    for (int n = t; n < NN; n += nt) cnt[n] = 0;   // reuse as cursor
    __syncthreads();
    int* osrc = g_ssrc + (slot*BB + b)*EE;
    float* onm = g_snorm + (slot*BB + b)*EE;
    for (int e = t; e < EE; e += nt) {
        int d = dst[e], s = src[e];
        int p = base[d] + atomicAdd(&cnt[d], 1);
        osrc[p] = s;
        onm[p]  = sdinv[s] * sdinv[d];
    }
}

// ---------------- build X0 = [embed | features] (positive branch) ----------------
__global__ void build_x0_kernel(const float* __restrict__ embA, const int* __restrict__ idxA,
                                const float* __restrict__ feat, const int* __restrict__ idxF) {
    int t = blockIdx.x * blockDim.x + threadIdx.x;   // MM*64 threads (float4 each)
    int row = t >> 6;
    int q   = t & 63;
    float4 v;
    if (q < 32) {
        int idx = idxA[row];
        v = *(const float4*)(embA + (size_t)idx*128 + q*4);
    } else {
        int idx = idxF[row];
        v = *(const float4*)(feat + (size_t)idx*128 + (q-32)*4);
    }
    *(float4*)(g_X0 + (size_t)row*256 + q*4) = v;
}

// ---------------- build X0 for BOTH malicious branches (rows 0..MM-1 = m1, MM.. = m2) ----
__global__ void build_x0_mal_kernel(const int* __restrict__ posidx1, const int* __restrict__ nodes1,
                                    const int* __restrict__ posidx2, const int* __restrict__ nodes2,
                                    const float* __restrict__ feat) {
    int t = blockIdx.x * blockDim.x + threadIdx.x;   // MM2*64 threads
    int row = t >> 6;
    int q   = t & 63;
    int half = row >= MM;
    int r    = row & (MM-1);
    int b    = r >> 9;
    float4 v;
    if (q < 32) {
        int idx = half ? posidx2[r] : posidx1[r];
        v = *(const float4*)(g_pos + ((size_t)b*NN + idx)*128 + q*4);
    } else {
        int idx = half ? nodes2[r] : nodes1[r];
        v = *(const float4*)(feat + (size_t)idx*128 + (q-32)*4);
    }
    *(float4*)(g_X0 + (size_t)row*256 + q*4) = v;
}

// ---------------- fp32x2 tiled GEMM: C[M,128] = act(A[M,K] @ W[K,128] + bias) -------
// BM=64 rows/block, 256 threads, thread computes 8 rows (4 packed pairs) x 4 cols.
__global__ __launch_bounds__(256) void gemm_kernel(const float* __restrict__ A,
                                                   const float* __restrict__ W,
                                                   const float* __restrict__ bias,
                                                   float* __restrict__ C,
                                                   int K, int act) {
    const int BM = 64, BK = 32;
    __shared__ float As[BK][BM];       // transposed A tile
    __shared__ float Ws[BK][128];
    int tid  = threadIdx.x;
    int row0 = blockIdx.x * BM;
    int tcol = tid & 31;               // cols tcol*4 .. +3
    int trow = tid >> 5;               // rows trow*8 .. +7

    unsigned long long acc[4][4];      // [row pair p -> rows 2p,2p+1][col c]
    #pragma unroll
    for (int p = 0; p < 4; p++)
        #pragma unroll
        for (int c = 0; c < 4; c++) acc[p][c] = 0ull;

    for (int kb = 0; kb < K; kb += BK) {
        #pragma unroll
        for (int l = 0; l < 2; l++) {
            int idx = tid + l*256;                 // 0..511
            int r   = idx >> 3;
            int c4  = idx & 7;
            float4 v = *(const float4*)(A + (size_t)(row0 + r)*K + kb + c4*4);
            As[c4*4+0][r] = v.x; As[c4*4+1][r] = v.y;
            As[c4*4+2][r] = v.z; As[c4*4+3][r] = v.w;
        }
        #pragma unroll
        for (int l = 0; l < 4; l++) {
            int idx = tid + l*256;                 // 0..1023
            int r   = idx >> 5;
            int c4  = idx & 31;
            *(float4*)&Ws[r][c4*4] = *(const float4*)(W + (size_t)(kb + r)*128 + c4*4);
        }
        __syncthreads();
        #pragma unroll
        for (int kk = 0; kk < BK; kk++) {
            ulonglong2 a01 = *(const ulonglong2*)&As[kk][trow*8];      // pairs (r0,r1),(r2,r3)
            ulonglong2 a23 = *(const ulonglong2*)&As[kk][trow*8 + 4];  // pairs (r4,r5),(r6,r7)
            float4 w = *(const float4*)&Ws[kk][tcol*4];
            unsigned long long wd0 = dup2(w.x), wd1 = dup2(w.y),
                               wd2 = dup2(w.z), wd3 = dup2(w.w);
            unsigned long long ap[4] = {a01.x, a01.y, a23.x, a23.y};
            #pragma unroll
            for (int p = 0; p < 4; p++) {
                acc[p][0] = fma2(ap[p], wd0, acc[p][0]);
                acc[p][1] = fma2(ap[p], wd1, acc[p][1]);
                acc[p][2] = fma2(ap[p], wd2, acc[p][2]);
                acc[p][3] = fma2(ap[p], wd3, acc[p][3]);
            }
        }
        __syncthreads();
    }
    float4 bb = make_float4(0.f,0.f,0.f,0.f);
    if (bias) bb = *(const float4*)(bias + tcol*4);
    #pragma unroll
    for (int p = 0; p < 4; p++) {
        float lo0,hi0, lo1,hi1, lo2,hi2, lo3,hi3;
        unpk(acc[p][0], lo0, hi0);
        unpk(acc[p][1], lo1, hi1);
        unpk(acc[p][2], lo2, hi2);
        unpk(acc[p][3], lo3, hi3);
        float4 olo = make_float4(lo0+bb.x, lo1+bb.y, lo2+bb.z, lo3+bb.w);
        float4 ohi = make_float4(hi0+bb.x, hi1+bb.y, hi2+bb.z, hi3+bb.w);
        if (act) {
            olo.x=fmaxf(olo.x,0.f); olo.y=fmaxf(olo.y,0.f);
            olo.z=fmaxf(olo.z,0.f); olo.w=fmaxf(olo.w,0.f);
            ohi.x=fmaxf(ohi.x,0.f); ohi.y=fmaxf(ohi.y,0.f);
            ohi.z=fmaxf(ohi.z,0.f); ohi.w=fmaxf(ohi.w,0.f);
        }
        *(float4*)(C + (size_t)(row0 + trow*8 + 2*p    )*128 + tcol*4) = olo;
        *(float4*)(C + (size_t)(row0 + trow*8 + 2*p + 1)*128 + tcol*4) = ohi;
    }
}

// ---------------- GCN aggregation via CSR gather: one warp per dst node ----------------
// slot_base: 0 -> positive (rows 0..MM), 1 -> merged malicious (rows 0..2MM, slots 1,2)
__global__ void agg_kernel(const float* __restrict__ h, int merged,
                           const float* __restrict__ bias,
                           float* __restrict__ outbuf, int relu, int nwarp) {
    int gw   = (blockIdx.x * blockDim.x + threadIdx.x) >> 5;
    int lane = threadIdx.x & 31;
    if (gw >= nwarp) return;
    int slot, b;
    if (merged) { slot = 1 + (gw >= MM); b = (gw & (MM-1)) >> 9; }
    else        { slot = 0;              b = gw >> 9; }
    int n = gw & (NN-1);
    const float* dinv  = g_dinv + slot*MM + b*NN;
    const int*   offs  = g_offs + (slot*BB + b)*(NN+1);
    const int*   ssrc  = g_ssrc + (slot*BB + b)*EE;
    const float* snorm = g_snorm + (slot*BB + b)*EE;
    const float* hb = h + (size_t)(gw >> 9)*NN*128;   // graph-block base

    float di = dinv[n];
    float4 hv = *(const float4*)(hb + (size_t)n*128 + lane*4);
    float self = di*di;
    float4 acc = make_float4(hv.x*self, hv.y*self, hv.z*self, hv.w*self);

    int beg = offs[n], end = offs[n+1];
    for (int j = beg; j < end; j++) {
        int   s  = ssrc[j];
        float nm = snorm[j];
        float4 v = *(const float4*)(hb + (size_t)s*128 + lane*4);
        acc.x += v.x*nm; acc.y += v.y*nm; acc.z += v.z*nm; acc.w += v.w*nm;
    }
    float4 bb = make_float4(0.f,0.f,0.f,0.f);
    if (bias) bb = *(const float4*)(bias + lane*4);
    float4 o = make_float4(acc.x+bb.x, acc.y+bb.y, acc.z+bb.z, acc.w+bb.w);
    if (relu) {
        o.x = fmaxf(o.x,0.f); o.y = fmaxf(o.y,0.f);
        o.z = fmaxf(o.z,0.f); o.w = fmaxf(o.w,0.f);
    }
    *(float4*)(outbuf + (size_t)gw*128 + lane*4) = o;
}

// ---------------- gather root rows ----------------
__global__ void gather_root_kernel(const float* __restrict__ src,
                                   const int* __restrict__ root_idx, int slot,
                                   int row_off) {
    int b = blockIdx.x;
    int lane = threadIdx.x;   // 32
    int r = root_idx[b];
    float4 v = *(const float4*)(src + ((size_t)row_off + (size_t)b*NN + r)*128 + lane*4);
    *(float4*)(g_roots + (size_t)(slot*BB + b)*HH + lane*4) = v;
}

// ---------------- score heads: sigmoid(relu(r@W1+b1)@W2+b2) ----------------
__global__ void score_kernel(const float* __restrict__ W1a, const float* __restrict__ b1a,
                             const float* __restrict__ W2a, const float* __restrict__ b2a,
                             const float* __restrict__ W1b, const float* __restrict__ b1b,
                             const float* __restrict__ W2b, const float* __restrict__ b2b,
                             float* __restrict__ out) {
    int combo = blockIdx.x;        // 0:(pos,A) 1:(pos,B) 2:(m1,A) 3:(m2,B)
    int b     = blockIdx.y;
    int t     = threadIdx.x;       // 128
    int rs = (combo < 2) ? 0 : (combo - 1);
    int ms = combo & 1;
    const float* W1 = ms ? W1b : W1a;
    const float* b1 = ms ? b1b : b1a;
    const float* W2 = ms ? W2b : W2a;
    const float* b2 = ms ? b2b : b2a;

    __shared__ float r[128];
    r[t] = g_roots[(size_t)(rs*BB + b)*HH + t];
    __syncthreads();

    float hsum = b1[t];
    #pragma unroll 8
    for (int k = 0; k < 128; k++) hsum += r[k] * W1[k*128 + t];
    hsum = fmaxf(hsum, 0.f);
    float p = hsum * W2[t];

    int lane = t & 31, warp = t >> 5;
    #pragma unroll
    for (int off = 16; off; off >>= 1) p += __shfl_down_sync(0xffffffff, p, off);
    __shared__ float ws[4];
    if (lane == 0) ws[warp] = p;
    __syncthreads();
    if (t == 0) {
        float s = ws[0] + ws[1] + ws[2] + ws[3] + b2[0];
        out[combo*BB + b] = 1.f / (1.f + expf(-s));
    }
}

// ---------------- host orchestration ----------------
extern "C" void kernel_launch(void* const* d_in, const int* in_sizes, int n_in,
                              void* d_out, int out_size) {
    const int* node_ids    = (const int*)d_in[0];
    const int* edge_pos    = (const int*)d_in[1];
    const int* root_idx    = (const int*)d_in[2];
    const int* mal_nodes1  = (const int*)d_in[3];
    const int* mal_posidx1 = (const int*)d_in[4];
    const int* edge_m1     = (const int*)d_in[5];
    const int* mal_nodes2  = (const int*)d_in[6];
    const int* mal_posidx2 = (const int*)d_in[7];
    const int* edge_m2     = (const int*)d_in[8];
    const float* embeddings = (const float*)d_in[9];
    const float* features   = (const float*)d_in[10];
    const float* fe_W1 = (const float*)d_in[11];
    const float* fe_b1 = (const float*)d_in[12];
    const float* fe_W2 = (const float*)d_in[13];
    const float* fe_b2 = (const float*)d_in[14];
    const float* g1_W  = (const float*)d_in[15];
    const float* g1_b  = (const float*)d_in[16];
    const float* g2_W  = (const float*)d_in[17];
    const float* g2_b  = (const float*)d_in[18];
    const float* mlp_W1  = (const float*)d_in[19];
    const float* mlp_b1  = (const float*)d_in[20];
    const float* mlp_W2  = (const float*)d_in[21];
    const float* mlp_b2  = (const float*)d_in[22];
    const float* mlp1_W1 = (const float*)d_in[23];
    const float* mlp1_b1 = (const float*)d_in[24];
    const float* mlp1_W2 = (const float*)d_in[25];
    const float* mlp1_b2 = (const float*)d_in[26];
    float* out = (float*)d_out;

    float *X0, *X1, *Ab, *Hb, *Pos;
    cudaGetSymbolAddress((void**)&X0,  g_X0);
    cudaGetSymbolAddress((void**)&X1,  g_X1);
    cudaGetSymbolAddress((void**)&Ab,  g_Ab);
    cudaGetSymbolAddress((void**)&Hb,  g_Hb);
    cudaGetSymbolAddress((void**)&Pos, g_pos);

    const int G1  = MM / 64;             // 512 gemm blocks (M = MM)
    const int G2  = MM2 / 64;            // 1024 gemm blocks (M = 2*MM)
    const int A1  = MM / 8;              // agg blocks, 8 warps each
    const int A2  = MM2 / 8;
    const int B1  = (MM  * 64) / 256;    // build_x0 grids
    const int B2  = (MM2 * 64) / 256;

    // CSR prep for all three edge sets
    prep_kernel<<<BB, 256>>>(edge_pos, 0);
    prep_kernel<<<BB, 256>>>(edge_m1, 1);
    prep_kernel<<<BB, 256>>>(edge_m2, 2);

    // ---- positive branch ----
    build_x0_kernel<<<B1, 256>>>(embeddings, node_ids, features, node_ids);
    gemm_kernel<<<G1, 256>>>(X0, fe_W1, fe_b1, X1, 256, 1);
    gemm_kernel<<<G1, 256>>>(X1, fe_W2, fe_b2, Ab, 128, 0);
    gemm_kernel<<<G1, 256>>>(Ab, g1_W, nullptr, Hb, 128, 0);
    agg_kernel <<<A1, 256>>>(Hb, 0, g1_b, X1, 1, MM);
    gemm_kernel<<<G1, 256>>>(X1, g2_W, nullptr, Hb, 128, 0);
    agg_kernel <<<A1, 256>>>(Hb, 0, g2_b, Pos, 0, MM);
    gather_root_kernel<<<BB, 32>>>(Pos, root_idx, 0, 0);

    // ---- merged malicious branches (rows [0,MM)=m1, [MM,2MM)=m2) ----
    build_x0_mal_kernel<<<B2, 256>>>(mal_posidx1, mal_nodes1, mal_posidx2, mal_nodes2, features);
    gemm_kernel<<<G2, 256>>>(X0, fe_W1, fe_b1, X1, 256, 1);
    gemm_kernel<<<G2, 256>>>(X1, fe_W2, fe_b2, Ab, 128, 0);
    gemm_kernel<<<G2, 256>>>(Ab, g1_W, nullptr, Hb, 128, 0);
    agg_kernel <<<A2, 256>>>(Hb, 1, g1_b, X1, 1, MM2);
    gemm_kernel<<<G2, 256>>>(X1, g2_W, nullptr, Hb, 128, 0);
    agg_kernel <<<A2, 256>>>(Hb, 1, g2_b, Ab, 0, MM2);
    gather_root_kernel<<<BB, 32>>>(Ab, root_idx, 1, 0);
    gather_root_kernel<<<BB, 32>>>(Ab, root_idx, 2, MM);

    // ---- score heads ----
    score_kernel<<<dim3(4, BB), 128>>>(mlp_W1, mlp_b1, mlp_W2, mlp_b2,
                                       mlp1_W1, mlp1_b1, mlp1_W2, mlp1_b2, out);
    (void)in_sizes; (void)n_in; (void)out_size;
}

// round 6
// speedup vs baseline: 1.5951x; 1.4248x over previous
#include <cuda_runtime.h>
#include <cuda_bf16.h>
#include <cstdint>
#include <math.h>

#define BB 64
#define NN 512
#define EE 8192
#define HH 128
#define MM (BB*NN)   // 32768
#define MM2 (2*MM)

// ---------------- scratch (static device allocations) ----------------
__device__ float g_X0 [(size_t)MM2*256];
__device__ float g_X1 [(size_t)MM2*128];
__device__ float g_Ab [(size_t)MM2*128];
__device__ float g_Hb [(size_t)MM2*128];
__device__ float g_pos[(size_t)MM*128];
__device__ float g_dinv [3*MM];
__device__ int   g_offs [3*BB*(NN+1)];
__device__ int   g_ssrc [3*BB*EE];
__device__ float g_snorm[3*BB*EE];
__device__ float g_roots[3*BB*HH];
// pre-split, pre-transposed weights: hi[n][k] then lo[n][k] (bf16 as ushort)
// fe1: 128*256*2 = 65536 ; fe2/g1/g2: 128*128*2 = 32768 each
__device__ unsigned short g_wt[65536 + 3*32768];

// ---------------- bf16 helpers ----------------
__device__ __forceinline__ unsigned short bfh(float x) {
    return __bfloat16_as_ushort(__float2bfloat16(x));
}

// mma.sync m16n8k16 row.col f32.bf16.bf16.f32, D += A*B
__device__ __forceinline__ void mma16816(float* d, const uint32_t* a, uint32_t b0, uint32_t b1) {
    asm volatile(
        "mma.sync.aligned.m16n8k16.row.col.f32.bf16.bf16.f32 "
        "{%0,%1,%2,%3}, {%4,%5,%6,%7}, {%8,%9}, {%0,%1,%2,%3};"
        : "+f"(d[0]), "+f"(d[1]), "+f"(d[2]), "+f"(d[3])
        : "r"(a[0]), "r"(a[1]), "r"(a[2]), "r"(a[3]), "r"(b0), "r"(b1));
}

// ---------------- weight prep: W[K][128] -> hi[n][K], lo[n][K] ----------------
__global__ void wprep_kernel(const float* __restrict__ W, unsigned short* __restrict__ dst, int K) {
    int t = blockIdx.x * 256 + threadIdx.x;
    if (t >= K * 128) return;
    int k = t >> 7;
    int n = t & 127;
    float x = W[(size_t)k * 128 + n];
    __nv_bfloat16 bh = __float2bfloat16(x);
    float rem = x - __bfloat162float(bh);
    dst[(size_t)n * K + k] = __bfloat16_as_ushort(bh);
    dst[(size_t)128 * K + (size_t)n * K + k] = bfh(rem);
}

// ---------------- HMMA GEMM: C[M,128] = act(A[M,K] @ W[K,128] + bias) ----------------
// CTA: 128x128 tile, 256 threads = 8 warps (4 m x 2 n), warp tile 32x64.
// bf16 3-product split: hi*hi + lo*hi + hi*lo, fp32 accum.
// smem per chunk(K=64): A hi/lo [128][72] bf16, B hi/lo [128 n][72 k] bf16 -> 73728 B
__global__ __launch_bounds__(256, 2)
void hmma_gemm_kernel(const float* __restrict__ A, const unsigned short* __restrict__ WT,
                      const float* __restrict__ bias, float* __restrict__ C, int K, int act) {
    extern __shared__ char smem[];
    char* sAh = smem;
    char* sAl = smem + 18432;
    char* sBh = smem + 36864;
    char* sBl = smem + 55296;

    int tid  = threadIdx.x;
    int lane = tid & 31;
    int wid  = tid >> 5;
    int row0 = blockIdx.x * 128;
    int mrow0 = (wid & 3) * 32;
    int ncol0 = (wid >> 2) * 64;
    int tq = lane >> 2;          // 0..7
    int tr = lane & 3;           // 0..3

    float acc[2][8][4];
    #pragma unroll
    for (int mt = 0; mt < 2; mt++)
        #pragma unroll
        for (int nt = 0; nt < 8; nt++)
            #pragma unroll
            for (int i = 0; i < 4; i++) acc[mt][nt][i] = 0.0f;

    const unsigned short* WH = WT;
    const unsigned short* WL = WT + (size_t)128 * K;

    int nchunk = K >> 6;
    for (int c = 0; c < nchunk; c++) {
        __syncthreads();
        // ---- A chunk: fp32 -> bf16 hi/lo into smem [128][72] ----
        #pragma unroll
        for (int i = 0; i < 8; i++) {
            int idx = tid + (i << 8);          // 0..2047
            int r = idx >> 4;
            int q = idx & 15;                  // float4 index, k = q*4
            float4 v = *(const float4*)(A + (size_t)(row0 + r) * K + (c << 6) + q * 4);
            unsigned short h0 = bfh(v.x), h1 = bfh(v.y), h2 = bfh(v.z), h3 = bfh(v.w);
            float l0 = v.x - __bfloat162float(__ushort_as_bfloat16(h0));
            float l1 = v.y - __bfloat162float(__ushort_as_bfloat16(h1));
            float l2 = v.z - __bfloat162float(__ushort_as_bfloat16(h2));
            float l3 = v.w - __bfloat162float(__ushort_as_bfloat16(h3));
            uint2 hv = make_uint2((uint32_t)h0 | ((uint32_t)h1 << 16),
                                  (uint32_t)h2 | ((uint32_t)h3 << 16));
            uint2 lv = make_uint2((uint32_t)bfh(l0) | ((uint32_t)bfh(l1) << 16),
                                  (uint32_t)bfh(l2) | ((uint32_t)bfh(l3) << 16));
            int off = r * 144 + q * 8;
            *(uint2*)(sAh + off) = hv;
            *(uint2*)(sAl + off) = lv;
        }
        // ---- B chunk: copy pre-split [n][k] rows into smem [128][72] ----
        #pragma unroll
        for (int i = 0; i < 4; i++) {
            int idx = tid + (i << 8);          // 0..1023
            int n = idx >> 3;
            int q = idx & 7;                   // 8-elem group, k = q*8
            size_t goff = (size_t)n * K + (c << 6) + q * 8;
            uint4 hv = *(const uint4*)(WH + goff);
            uint4 lv = *(const uint4*)(WL + goff);
            int off = n * 144 + q * 16;
            *(uint4*)(sBh + off) = hv;
            *(uint4*)(sBl + off) = lv;
        }
        __syncthreads();

        // ---- fragment compute ----
        #pragma unroll
        for (int ks = 0; ks < 4; ks++) {
            uint32_t ah[2][4], al[2][4];
            #pragma unroll
            for (int mt = 0; mt < 2; mt++) {
                int base = (mrow0 + mt * 16 + tq) * 144 + ks * 32 + tr * 4;
                ah[mt][0] = *(const uint32_t*)(sAh + base);
                ah[mt][1] = *(const uint32_t*)(sAh + base + 1152);   // +8 rows
                ah[mt][2] = *(const uint32_t*)(sAh + base + 16);     // +8 k
                ah[mt][3] = *(const uint32_t*)(sAh + base + 1168);
                al[mt][0] = *(const uint32_t*)(sAl + base);
                al[mt][1] = *(const uint32_t*)(sAl + base + 1152);
                al[mt][2] = *(const uint32_t*)(sAl + base + 16);
                al[mt][3] = *(const uint32_t*)(sAl + base + 1168);
            }
            #pragma unroll
            for (int nt = 0; nt < 8; nt++) {
                int bbase = (ncol0 + nt * 8 + tq) * 144 + ks * 32 + tr * 4;
                uint32_t bh0 = *(const uint32_t*)(sBh + bbase);
                uint32_t bh1 = *(const uint32_t*)(sBh + bbase + 16);
                uint32_t bl0 = *(const uint32_t*)(sBl + bbase);
                uint32_t bl1 = *(const uint32_t*)(sBl + bbase + 16);
                #pragma unroll
                for (int mt = 0; mt < 2; mt++) {
                    mma16816(acc[mt][nt], ah[mt], bh0, bh1);   // hi*hi
                    mma16816(acc[mt][nt], al[mt], bh0, bh1);   // lo*hi
                    mma16816(acc[mt][nt], ah[mt], bl0, bl1);   // hi*lo
                }
            }
        }
    }

    // ---- epilogue: bias + act, direct float2 stores ----
    #pragma unroll
    for (int nt = 0; nt < 8; nt++) {
        int col = ncol0 + nt * 8 + tr * 2;
        float2 bb = make_float2(0.0f, 0.0f);
        if (bias) bb = *(const float2*)(bias + col);
        #pragma unroll
        for (int mt = 0; mt < 2; mt++) {
            int r0 = row0 + mrow0 + mt * 16 + tq;
            float2 v0 = make_float2(acc[mt][nt][0] + bb.x, acc[mt][nt][1] + bb.y);
            float2 v1 = make_float2(acc[mt][nt][2] + bb.x, acc[mt][nt][3] + bb.y);
            if (act) {
                v0.x = fmaxf(v0.x, 0.0f); v0.y = fmaxf(v0.y, 0.0f);
                v1.x = fmaxf(v1.x, 0.0f); v1.y = fmaxf(v1.y, 0.0f);
            }
            *(float2*)(C + (size_t)r0 * 128 + col) = v0;
            *(float2*)(C + (size_t)(r0 + 8) * 128 + col) = v1;
        }
    }
}

// ---------------- prep: degrees, dinv, dst-sorted CSR + norms ----------------
__global__ void prep_kernel(const int* __restrict__ edges, int slot) {
    int b = blockIdx.x;
    const int* src = edges + (size_t)b*2*EE;
    const int* dst = src + EE;
    __shared__ int   cnt[NN];
    __shared__ float sdinv[NN];
    __shared__ int   base[NN+1];
    int t = threadIdx.x, nt = blockDim.x;

    for (int n = t; n < NN; n += nt) cnt[n] = 0;
    __syncthreads();
    for (int e = t; e < EE; e += nt) atomicAdd(&cnt[dst[e]], 1);
    __syncthreads();
    for (int n = t; n < NN; n += nt) {
        float d = (float)(cnt[n] + 1);
        float di = rsqrtf(d);
        sdinv[n] = di;
        g_dinv[slot*MM + b*NN + n] = di;
    }
    __syncthreads();
    if (t == 0) {
        int s = 0;
        for (int n = 0; n < NN; n++) { base[n] = s; s += cnt[n]; }
        base[NN] = s;
    }
    __syncthreads();
    for (int n = t; n <= NN; n += nt)
        g_offs[(slot*BB + b)*(NN+1) + n] = base[n];
    for (int n = t; n < NN; n += nt) cnt[n] = 0;
    __syncthreads();
    int* osrc = g_ssrc + (slot*BB + b)*EE;
    float* onm = g_snorm + (slot*BB + b)*EE;
    for (int e = t; e < EE; e += nt) {
        int d = dst[e], s = src[e];
        int p = base[d] + atomicAdd(&cnt[d], 1);
        osrc[p] = s;
        onm[p]  = sdinv[s] * sdinv[d];
    }
}

// ---------------- build X0 = [embed | features] (positive branch) ----------------
__global__ void build_x0_kernel(const float* __restrict__ embA, const int* __restrict__ idxA,
                                const float* __restrict__ feat, const int* __restrict__ idxF) {
    int t = blockIdx.x * blockDim.x + threadIdx.x;
    int row = t >> 6;
    int q   = t & 63;
    float4 v;
    if (q < 32) {
        int idx = idxA[row];
        v = *(const float4*)(embA + (size_t)idx*128 + q*4);
    } else {
        int idx = idxF[row];
        v = *(const float4*)(feat + (size_t)idx*128 + (q-32)*4);
    }
    *(float4*)(g_X0 + (size_t)row*256 + q*4) = v;
}

// ---------------- build X0 for BOTH malicious branches ----------------
__global__ void build_x0_mal_kernel(const int* __restrict__ posidx1, const int* __restrict__ nodes1,
                                    const int* __restrict__ posidx2, const int* __restrict__ nodes2,
                                    const float* __restrict__ feat) {
    int t = blockIdx.x * blockDim.x + threadIdx.x;
    int row = t >> 6;
    int q   = t & 63;
    int half = row >= MM;
    int r    = row & (MM-1);
    int b    = r >> 9;
    float4 v;
    if (q < 32) {
        int idx = half ? posidx2[r] : posidx1[r];
        v = *(const float4*)(g_pos + ((size_t)b*NN + idx)*128 + q*4);
    } else {
        int idx = half ? nodes2[r] : nodes1[r];
        v = *(const float4*)(feat + (size_t)idx*128 + (q-32)*4);
    }
    *(float4*)(g_X0 + (size_t)row*256 + q*4) = v;
}

// ---------------- GCN aggregation via CSR gather: one warp per dst node ----------------
__global__ void agg_kernel(const float* __restrict__ h, int merged,
                           const float* __restrict__ bias,
                           float* __restrict__ outbuf, int relu, int nwarp) {
    int gw   = (blockIdx.x * blockDim.x + threadIdx.x) >> 5;
    int lane = threadIdx.x & 31;
    if (gw >= nwarp) return;
    int slot, b;
    if (merged) { slot = 1 + (gw >= MM); b = (gw & (MM-1)) >> 9; }
    else        { slot = 0;              b = gw >> 9; }
    int n = gw & (NN-1);
    const float* dinv  = g_dinv + slot*MM + b*NN;
    const int*   offs  = g_offs + (slot*BB + b)*(NN+1);
    const int*   ssrc  = g_ssrc + (slot*BB + b)*EE;
    const float* snorm = g_snorm + (slot*BB + b)*EE;
    const float* hb = h + (size_t)(gw >> 9)*NN*128;

    float di = dinv[n];
    float4 hv = *(const float4*)(hb + (size_t)n*128 + lane*4);
    float self = di*di;
    float4 acc = make_float4(hv.x*self, hv.y*self, hv.z*self, hv.w*self);

    int beg = offs[n], end = offs[n+1];
    for (int j = beg; j < end; j++) {
        int   s  = ssrc[j];
        float nm = snorm[j];
        float4 v = *(const float4*)(hb + (size_t)s*128 + lane*4);
        acc.x += v.x*nm; acc.y += v.y*nm; acc.z += v.z*nm; acc.w += v.w*nm;
    }
    float4 bb = make_float4(0.f,0.f,0.f,0.f);
    if (bias) bb = *(const float4*)(bias + lane*4);
    float4 o = make_float4(acc.x+bb.x, acc.y+bb.y, acc.z+bb.z, acc.w+bb.w);
    if (relu) {
        o.x = fmaxf(o.x,0.f); o.y = fmaxf(o.y,0.f);
        o.z = fmaxf(o.z,0.f); o.w = fmaxf(o.w,0.f);
    }
    *(float4*)(outbuf + (size_t)gw*128 + lane*4) = o;
}

// ---------------- gather root rows ----------------
__global__ void gather_root_kernel(const float* __restrict__ src,
                                   const int* __restrict__ root_idx, int slot,
                                   int row_off) {
    int b = blockIdx.x;
    int lane = threadIdx.x;
    int r = root_idx[b];
    float4 v = *(const float4*)(src + ((size_t)row_off + (size_t)b*NN + r)*128 + lane*4);
    *(float4*)(g_roots + (size_t)(slot*BB + b)*HH + lane*4) = v;
}

// ---------------- score heads ----------------
__global__ void score_kernel(const float* __restrict__ W1a, const float* __restrict__ b1a,
                             const float* __restrict__ W2a, const float* __restrict__ b2a,
                             const float* __restrict__ W1b, const float* __restrict__ b1b,
                             const float* __restrict__ W2b, const float* __restrict__ b2b,
                             float* __restrict__ out) {
    int combo = blockIdx.x;
    int b     = blockIdx.y;
    int t     = threadIdx.x;
    int rs = (combo < 2) ? 0 : (combo - 1);
    int ms = combo & 1;
    const float* W1 = ms ? W1b : W1a;
    const float* b1 = ms ? b1b : b1a;
    const float* W2 = ms ? W2b : W2a;
    const float* b2 = ms ? b2b : b2a;

    __shared__ float r[128];
    r[t] = g_roots[(size_t)(rs*BB + b)*HH + t];
    __syncthreads();

    float hsum = b1[t];
    #pragma unroll 8
    for (int k = 0; k < 128; k++) hsum += r[k] * W1[k*128 + t];
    hsum = fmaxf(hsum, 0.f);
    float p = hsum * W2[t];

    int lane = t & 31, warp = t >> 5;
    #pragma unroll
    for (int off = 16; off; off >>= 1) p += __shfl_down_sync(0xffffffff, p, off);
    __shared__ float ws[4];
    if (lane == 0) ws[warp] = p;
    __syncthreads();
    if (t == 0) {
        float s = ws[0] + ws[1] + ws[2] + ws[3] + b2[0];
        out[combo*BB + b] = 1.f / (1.f + expf(-s));
    }
}

// ---------------- host orchestration ----------------
extern "C" void kernel_launch(void* const* d_in, const int* in_sizes, int n_in,
                              void* d_out, int out_size) {
    const int* node_ids    = (const int*)d_in[0];
    const int* edge_pos    = (const int*)d_in[1];
    const int* root_idx    = (const int*)d_in[2];
    const int* mal_nodes1  = (const int*)d_in[3];
    const int* mal_posidx1 = (const int*)d_in[4];
    const int* edge_m1     = (const int*)d_in[5];
    const int* mal_nodes2  = (const int*)d_in[6];
    const int* mal_posidx2 = (const int*)d_in[7];
    const int* edge_m2     = (const int*)d_in[8];
    const float* embeddings = (const float*)d_in[9];
    const float* features   = (const float*)d_in[10];
    const float* fe_W1 = (const float*)d_in[11];
    const float* fe_b1 = (const float*)d_in[12];
    const float* fe_W2 = (const float*)d_in[13];
    const float* fe_b2 = (const float*)d_in[14];
    const float* g1_W  = (const float*)d_in[15];
    const float* g1_b  = (const float*)d_in[16];
    const float* g2_W  = (const float*)d_in[17];
    const float* g2_b  = (const float*)d_in[18];
    const float* mlp_W1  = (const float*)d_in[19];
    const float* mlp_b1  = (const float*)d_in[20];
    const float* mlp_W2  = (const float*)d_in[21];
    const float* mlp_b2  = (const float*)d_in[22];
    const float* mlp1_W1 = (const float*)d_in[23];
    const float* mlp1_b1 = (const float*)d_in[24];
    const float* mlp1_W2 = (const float*)d_in[25];
    const float* mlp1_b2 = (const float*)d_in[26];
    float* out = (float*)d_out;

    float *X0, *X1, *Ab, *Hb, *Pos;
    unsigned short* WT;
    cudaGetSymbolAddress((void**)&X0,  g_X0);
    cudaGetSymbolAddress((void**)&X1,  g_X1);
    cudaGetSymbolAddress((void**)&Ab,  g_Ab);
    cudaGetSymbolAddress((void**)&Hb,  g_Hb);
    cudaGetSymbolAddress((void**)&Pos, g_pos);
    cudaGetSymbolAddress((void**)&WT,  g_wt);

    unsigned short* wt_fe1 = WT;
    unsigned short* wt_fe2 = WT + 65536;
    unsigned short* wt_g1  = WT + 98304;
    unsigned short* wt_g2  = WT + 131072;

    const int SMEMSZ = 73728;
    cudaFuncSetAttribute(hmma_gemm_kernel,
                         cudaFuncAttributeMaxDynamicSharedMemorySize, SMEMSZ);

    const int G1  = MM  / 128;           // 256 gemm blocks
    const int G2  = MM2 / 128;           // 512
    const int A1  = MM / 8;
    const int A2  = MM2 / 8;
    const int B1  = (MM  * 64) / 256;
    const int B2  = (MM2 * 64) / 256;

    wprep_kernel<<<128, 256>>>(fe_W1, wt_fe1, 256);
    wprep_kernel<<<64, 256>>>(fe_W2, wt_fe2, 128);
    wprep_kernel<<<64, 256>>>(g1_W,  wt_g1,  128);
    wprep_kernel<<<64, 256>>>(g2_W,  wt_g2,  128);
    prep_kernel<<<BB, 256>>>(edge_pos, 0);
    prep_kernel<<<BB, 256>>>(edge_m1, 1);
    prep_kernel<<<BB, 256>>>(edge_m2, 2);

    // ---- positive branch ----
    build_x0_kernel<<<B1, 256>>>(embeddings, node_ids, features, node_ids);
    hmma_gemm_kernel<<<G1, 256, SMEMSZ>>>(X0, wt_fe1, fe_b1, X1, 256, 1);
    hmma_gemm_kernel<<<G1, 256, SMEMSZ>>>(X1, wt_fe2, fe_b2, Ab, 128, 0);
    hmma_gemm_kernel<<<G1, 256, SMEMSZ>>>(Ab, wt_g1, 0, Hb, 128, 0);
    agg_kernel <<<A1, 256>>>(Hb, 0, g1_b, X1, 1, MM);
    hmma_gemm_kernel<<<G1, 256, SMEMSZ>>>(X1, wt_g2, 0, Hb, 128, 0);
    agg_kernel <<<A1, 256>>>(Hb, 0, g2_b, Pos, 0, MM);
    gather_root_kernel<<<BB, 32>>>(Pos, root_idx, 0, 0);

    // ---- merged malicious branches ----
    build_x0_mal_kernel<<<B2, 256>>>(mal_posidx1, mal_nodes1, mal_posidx2, mal_nodes2, features);
    hmma_gemm_kernel<<<G2, 256, SMEMSZ>>>(X0, wt_fe1, fe_b1, X1, 256, 1);
    hmma_gemm_kernel<<<G2, 256, SMEMSZ>>>(X1, wt_fe2, fe_b2, Ab, 128, 0);
    hmma_gemm_kernel<<<G2, 256, SMEMSZ>>>(Ab, wt_g1, 0, Hb, 128, 0);
    agg_kernel <<<A2, 256>>>(Hb, 1, g1_b, X1, 1, MM2);
    hmma_gemm_kernel<<<G2, 256, SMEMSZ>>>(X1, wt_g2, 0, Hb, 128, 0);
    agg_kernel <<<A2, 256>>>(Hb, 1, g2_b, Ab, 0, MM2);
    gather_root_kernel<<<BB, 32>>>(Ab, root_idx, 1, 0);
    gather_root_kernel<<<BB, 32>>>(Ab, root_idx, 2, MM);

    // ---- score heads ----
    score_kernel<<<dim3(4, BB), 128>>>(mlp_W1, mlp_b1, mlp_W2, mlp_b2,
                                       mlp1_W1, mlp1_b1, mlp1_W2, mlp1_b2, out);
    (void)in_sizes; (void)n_in; (void)out_size;
}